// round 2
// baseline (speedup 1.0000x reference)
#include <cuda_runtime.h>
#include <cstdint>

// ---------------- problem constants ----------------
#define N_NODES   100000
#define E_EDGES   1600000
#define TOT_E     (E_EDGES + N_NODES)   // with self loops = 1,700,000
#define F_DIM     128
#define H_DIM     64
#define K_CL      16
#define NEG_SLOPE 0.2f

// ---------------- device scratch (allocation-free) ----------------
__device__ float g_y1[(size_t)N_NODES * 128];   // [xl1 | xr1]  (N,128)
__device__ float g_acc1[(size_t)N_NODES * 64];  // sum w * xl1[src]
__device__ float g_denom1[N_NODES];
__device__ float g_h[(size_t)N_NODES * 64];     // elu output of layer 1
__device__ float g_y2[(size_t)N_NODES * 32];    // [xl2 | xr2]  (N,32)
__device__ float g_acc2[(size_t)N_NODES * 16];
__device__ float g_denom2[N_NODES];
__device__ float g_Wc1[128 * 128];              // [W1l | W1r] packed (K=128, N=128)
__device__ float g_Wc2[64 * 32];                // [W2l | W2r] packed (K=64, N=32)
__device__ int   g_idx64;                       // 1 if edge indices are int64

// ---------------- utility kernels ----------------
__global__ void detect_idx_kernel(const void* ei) {
    // int32 index pairs reinterpreted as int64 are >= 2^32 unless the high
    // word happens to be 0 (p ~ 1e-5 per element) -> 32 probes is decisive.
    const long long* p = (const long long*)ei;
    bool ok = true;
    for (int i = 0; i < 32; i++) {
        long long v = p[i];
        if (v < 0 || v >= N_NODES) ok = false;
    }
    g_idx64 = ok ? 1 : 0;
}

__global__ void pack_w_kernel(const float* __restrict__ W1l, const float* __restrict__ W1r,
                              const float* __restrict__ W2l, const float* __restrict__ W2r) {
    int t = blockIdx.x * blockDim.x + threadIdx.x;
    if (t < 128 * 128) {
        int k = t >> 7, n = t & 127;
        g_Wc1[t] = (n < 64) ? W1l[k * 64 + n] : W1r[k * 64 + (n - 64)];
    }
    if (t < 64 * 32) {
        int k = t >> 5, n = t & 31;
        g_Wc2[t] = (n < 16) ? W2l[k * 16 + n] : W2r[k * 16 + (n - 16)];
    }
}

__global__ void zero_all_kernel() {
    int t = blockIdx.x * blockDim.x + threadIdx.x;
    float4 z = make_float4(0.f, 0.f, 0.f, 0.f);
    if (t < (N_NODES * 64) / 4) ((float4*)g_acc1)[t] = z;
    if (t < (N_NODES * 16) / 4) ((float4*)g_acc2)[t] = z;
    if (t < N_NODES / 4) {
        ((float4*)g_denom1)[t] = z;
        ((float4*)g_denom2)[t] = z;
    }
}

// ---------------- GEMM 1: y1 = X @ Wc1   (M=100000, K=128, N=128) ----------------
__global__ __launch_bounds__(256) void sgemm1_kernel(const float* __restrict__ A, int M) {
    constexpr int BM = 128, BN = 128, BK = 8, TM = 8, TN = 8;
    __shared__ float As[BK][BM];
    __shared__ float Bs[BK][BN];

    int tid = threadIdx.x;
    int blockRow = blockIdx.x * BM;

    int aRow = tid >> 1;            // 0..127
    int aCol = (tid & 1) * 4;       // 0 or 4
    int bRow = tid >> 5;            // 0..7
    int bCol = (tid & 31) * 4;      // 0..124

    int tRow = (tid >> 4) * TM;
    int tCol = (tid & 15) * TN;

    float acc[TM][TN];
#pragma unroll
    for (int i = 0; i < TM; i++)
#pragma unroll
        for (int j = 0; j < TN; j++) acc[i][j] = 0.f;

    for (int k0 = 0; k0 < 128; k0 += BK) {
        float4 av = make_float4(0.f, 0.f, 0.f, 0.f);
        int gr = blockRow + aRow;
        if (gr < M) av = *(const float4*)(A + (size_t)gr * 128 + k0 + aCol);
        As[aCol + 0][aRow] = av.x;
        As[aCol + 1][aRow] = av.y;
        As[aCol + 2][aRow] = av.z;
        As[aCol + 3][aRow] = av.w;

        *(float4*)(&Bs[bRow][bCol]) = *(const float4*)(g_Wc1 + (size_t)(k0 + bRow) * 128 + bCol);
        __syncthreads();

        float ar[TM], br[TN];
#pragma unroll
        for (int k = 0; k < BK; k++) {
#pragma unroll
            for (int i = 0; i < TM; i++) ar[i] = As[k][tRow + i];
#pragma unroll
            for (int j = 0; j < TN; j++) br[j] = Bs[k][tCol + j];
#pragma unroll
            for (int i = 0; i < TM; i++)
#pragma unroll
                for (int j = 0; j < TN; j++) acc[i][j] = fmaf(ar[i], br[j], acc[i][j]);
        }
        __syncthreads();
    }

#pragma unroll
    for (int i = 0; i < TM; i++) {
        int gr = blockRow + tRow + i;
        if (gr < M) {
            *(float4*)(g_y1 + (size_t)gr * 128 + tCol)     = make_float4(acc[i][0], acc[i][1], acc[i][2], acc[i][3]);
            *(float4*)(g_y1 + (size_t)gr * 128 + tCol + 4) = make_float4(acc[i][4], acc[i][5], acc[i][6], acc[i][7]);
    }
    }
}

// ---------------- edge index fetch ----------------
__device__ __forceinline__ void load_edge(const void* ei, int e, int& src, int& dst) {
    if (e >= E_EDGES) { src = dst = e - E_EDGES; return; }
    if (g_idx64) {
        const long long* p = (const long long*)ei;
        src = (int)p[e];
        dst = (int)p[(size_t)E_EDGES + e];
    } else {
        const int* p = (const int*)ei;
        src = p[e];
        dst = p[E_EDGES + e];
    }
}

__device__ __forceinline__ float lrelu(float x) { return x > 0.f ? x : NEG_SLOPE * x; }

// ---------------- edge pass 1: 16 lanes / edge ----------------
__global__ __launch_bounds__(256) void edge1_kernel(const void* __restrict__ ei,
                                                    const float* __restrict__ a1) {
    int g = blockIdx.x * blockDim.x + threadIdx.x;
    int e = g >> 4;
    int lane = g & 15;
    if (e >= TOT_E) return;

    int src, dst;
    load_edge(ei, e, src, dst);

    float4 xl = *(const float4*)(g_y1 + (size_t)src * 128 + lane * 4);
    float4 xr = *(const float4*)(g_y1 + (size_t)dst * 128 + 64 + lane * 4);
    float4 av = *(const float4*)(a1 + lane * 4);

    float p = lrelu(xl.x + xr.x) * av.x;
    p = fmaf(lrelu(xl.y + xr.y), av.y, p);
    p = fmaf(lrelu(xl.z + xr.z), av.z, p);
    p = fmaf(lrelu(xl.w + xr.w), av.w, p);

    p += __shfl_xor_sync(0xffffffffu, p, 8);
    p += __shfl_xor_sync(0xffffffffu, p, 4);
    p += __shfl_xor_sync(0xffffffffu, p, 2);
    p += __shfl_xor_sync(0xffffffffu, p, 1);

    float w = expf(p);   // max-free softmax: |p| is tiny here, fp32-safe

    if (lane == 0) atomicAdd(g_denom1 + dst, w);

    float4 contrib = make_float4(w * xl.x, w * xl.y, w * xl.z, w * xl.w);
    atomicAdd((float4*)(g_acc1 + (size_t)dst * 64 + lane * 4), contrib);
}

// ---------------- node pass 1: h = elu(acc1/denom1 + b1) ----------------
__global__ __launch_bounds__(256) void node1_kernel(const float* __restrict__ b1) {
    int t = blockIdx.x * blockDim.x + threadIdx.x;
    if (t >= N_NODES * 16) return;
    int i = t >> 4, c = t & 15;

    float4 v = ((const float4*)g_acc1)[(size_t)i * 16 + c];
    float inv = 1.f / g_denom1[i];
    float4 bb = *(const float4*)(b1 + c * 4);

    float x0 = fmaf(v.x, inv, bb.x);
    float x1 = fmaf(v.y, inv, bb.y);
    float x2 = fmaf(v.z, inv, bb.z);
    float x3 = fmaf(v.w, inv, bb.w);

    float4 h;
    h.x = x0 > 0.f ? x0 : expm1f(x0);
    h.y = x1 > 0.f ? x1 : expm1f(x1);
    h.z = x2 > 0.f ? x2 : expm1f(x2);
    h.w = x3 > 0.f ? x3 : expm1f(x3);
    ((float4*)g_h)[(size_t)i * 16 + c] = h;
}

// ---------------- GEMM 2: y2 = h @ Wc2  (M=100000, K=64, N=32): warp per row ----------------
__global__ __launch_bounds__(256) void gemm2_kernel() {
    __shared__ float Ws[64 * 32];
    for (int i = threadIdx.x; i < 64 * 32; i += blockDim.x) Ws[i] = g_Wc2[i];
    __syncthreads();

    int row = (blockIdx.x * blockDim.x + threadIdx.x) >> 5;
    int lane = threadIdx.x & 31;
    if (row >= N_NODES) return;

    const float* hr = g_h + (size_t)row * 64;
    float h0 = hr[lane];
    float h1 = hr[lane + 32];

    float acc = 0.f;
#pragma unroll
    for (int k = 0; k < 32; k++) {
        float hv = __shfl_sync(0xffffffffu, h0, k);
        acc = fmaf(hv, Ws[k * 32 + lane], acc);
    }
#pragma unroll
    for (int k = 0; k < 32; k++) {
        float hv = __shfl_sync(0xffffffffu, h1, k);
        acc = fmaf(hv, Ws[(k + 32) * 32 + lane], acc);
    }
    g_y2[(size_t)row * 32 + lane] = acc;
}

// ---------------- edge pass 2: 4 lanes / edge ----------------
__global__ __launch_bounds__(256) void edge2_kernel(const void* __restrict__ ei,
                                                    const float* __restrict__ a2) {
    int g = blockIdx.x * blockDim.x + threadIdx.x;
    int e = g >> 2;
    int lane = g & 3;
    if (e >= TOT_E) return;

    int src, dst;
    load_edge(ei, e, src, dst);

    float4 xl = *(const float4*)(g_y2 + (size_t)src * 32 + lane * 4);
    float4 xr = *(const float4*)(g_y2 + (size_t)dst * 32 + 16 + lane * 4);
    float4 av = *(const float4*)(a2 + lane * 4);

    float p = lrelu(xl.x + xr.x) * av.x;
    p = fmaf(lrelu(xl.y + xr.y), av.y, p);
    p = fmaf(lrelu(xl.z + xr.z), av.z, p);
    p = fmaf(lrelu(xl.w + xr.w), av.w, p);

    p += __shfl_xor_sync(0xffffffffu, p, 2);
    p += __shfl_xor_sync(0xffffffffu, p, 1);

    float w = expf(p);

    if (lane == 0) atomicAdd(g_denom2 + dst, w);

    float4 contrib = make_float4(w * xl.x, w * xl.y, w * xl.z, w * xl.w);
    atomicAdd((float4*)(g_acc2 + (size_t)dst * 16 + lane * 4), contrib);
}

// ---------------- final: softmax(acc2/denom2 + b2) over 16 classes ----------------
__global__ __launch_bounds__(256) void final_kernel(const float* __restrict__ b2,
                                                    float* __restrict__ out) {
    int t = blockIdx.x * blockDim.x + threadIdx.x;
    if (t >= N_NODES * 16) return;
    int i = t >> 4, l = t & 15;

    float v = g_acc2[(size_t)i * 16 + l] / g_denom2[i] + b2[l];

    float m = v;
    m = fmaxf(m, __shfl_xor_sync(0xffffffffu, m, 8));
    m = fmaxf(m, __shfl_xor_sync(0xffffffffu, m, 4));
    m = fmaxf(m, __shfl_xor_sync(0xffffffffu, m, 2));
    m = fmaxf(m, __shfl_xor_sync(0xffffffffu, m, 1));

    float ex = expf(v - m);
    float s = ex;
    s += __shfl_xor_sync(0xffffffffu, s, 8);
    s += __shfl_xor_sync(0xffffffffu, s, 4);
    s += __shfl_xor_sync(0xffffffffu, s, 2);
    s += __shfl_xor_sync(0xffffffffu, s, 1);

    out[t] = ex / s;
}

// ---------------- launch ----------------
extern "C" void kernel_launch(void* const* d_in, const int* in_sizes, int n_in,
                              void* d_out, int out_size) {
    const float* X   = (const float*)d_in[0];
    const void*  ei  = d_in[1];
    // d_in[2] = batch (unused)
    const float* W1l = (const float*)d_in[3];
    const float* W1r = (const float*)d_in[4];
    const float* a1  = (const float*)d_in[5];
    const float* b1  = (const float*)d_in[6];
    const float* W2l = (const float*)d_in[7];
    const float* W2r = (const float*)d_in[8];
    const float* a2  = (const float*)d_in[9];
    const float* b2  = (const float*)d_in[10];
    float* out = (float*)d_out;

    detect_idx_kernel<<<1, 1>>>(ei);
    pack_w_kernel<<<64, 256>>>(W1l, W1r, W2l, W2r);
    zero_all_kernel<<<(N_NODES * 64 / 4 + 255) / 256, 256>>>();

    sgemm1_kernel<<<(N_NODES + 127) / 128, 256>>>(X, N_NODES);

    {
        long long threads = (long long)TOT_E * 16;
        edge1_kernel<<<(unsigned)((threads + 255) / 256), 256>>>(ei, a1);
    }

    node1_kernel<<<(N_NODES * 16 + 255) / 256, 256>>>(b1);

    gemm2_kernel<<<(N_NODES * 32 + 255) / 256, 256>>>();

    {
        long long threads = (long long)TOT_E * 4;
        edge2_kernel<<<(unsigned)((threads + 255) / 256), 256>>>(ei, a2);
    }

    final_kernel<<<(N_NODES * 16 + 255) / 256, 256>>>(b2, out);
}

// round 3
// speedup vs baseline: 1.0342x; 1.0342x over previous
#include <cuda_runtime.h>
#include <cstdint>

// ---------------- problem constants ----------------
#define N_NODES   100000
#define E_EDGES   1600000
#define TOT_E     (E_EDGES + N_NODES)   // with self loops = 1,700,000
#define F_DIM     128
#define H_DIM     64
#define K_CL      16
#define NEG_SLOPE 0.2f

// ---------------- device scratch (allocation-free) ----------------
__device__ float g_y1[(size_t)N_NODES * 128];   // [xl1 | xr1]  (N,128)
__device__ float g_acc1[(size_t)N_NODES * 64];  // sum w * xl1[src]
__device__ float g_denom1[N_NODES];
__device__ float g_y2[(size_t)N_NODES * 32];    // [xl2 | xr2]  (N,32)
__device__ float g_acc2[(size_t)N_NODES * 16];
__device__ float g_denom2[N_NODES];
__device__ float g_Wc1[128 * 128];              // [W1l | W1r] packed (K=128, N=128)
__device__ float g_Wc2[64 * 32];                // [W2l | W2r] packed (K=64, N=32)
__device__ int   g_idx64;                       // 1 if edge indices are int64

// ---------------- packed fp32x2 helpers (Blackwell FFMA2) ----------------
__device__ __forceinline__ void ffma2(uint64_t& d, uint64_t a, uint64_t b) {
    asm("fma.rn.f32x2 %0, %1, %2, %0;" : "+l"(d) : "l"(a), "l"(b));
}
__device__ __forceinline__ uint64_t pack_dup(float x) {
    uint64_t r;
    asm("mov.b64 %0, {%1, %1};" : "=l"(r) : "f"(x));
    return r;
}
__device__ __forceinline__ void unpack2(uint64_t v, float& lo, float& hi) {
    asm("mov.b64 {%0, %1}, %2;" : "=f"(lo), "=f"(hi) : "l"(v));
}

// ---------------- utility kernels ----------------
__global__ void detect_idx_kernel(const void* ei) {
    const long long* p = (const long long*)ei;
    bool ok = true;
    for (int i = 0; i < 32; i++) {
        long long v = p[i];
        if (v < 0 || v >= N_NODES) ok = false;
    }
    g_idx64 = ok ? 1 : 0;
}

__global__ void pack_w_kernel(const float* __restrict__ W1l, const float* __restrict__ W1r,
                              const float* __restrict__ W2l, const float* __restrict__ W2r) {
    int t = blockIdx.x * blockDim.x + threadIdx.x;
    if (t < 128 * 128) {
        int k = t >> 7, n = t & 127;
        g_Wc1[t] = (n < 64) ? W1l[k * 64 + n] : W1r[k * 64 + (n - 64)];
    }
    if (t < 64 * 32) {
        int k = t >> 5, n = t & 31;
        g_Wc2[t] = (n < 16) ? W2l[k * 16 + n] : W2r[k * 16 + (n - 16)];
    }
}

__global__ void zero_all_kernel() {
    int t = blockIdx.x * blockDim.x + threadIdx.x;
    float4 z = make_float4(0.f, 0.f, 0.f, 0.f);
    if (t < (N_NODES * 64) / 4) ((float4*)g_acc1)[t] = z;
    if (t < (N_NODES * 16) / 4) ((float4*)g_acc2)[t] = z;
    if (t < N_NODES / 4) {
        ((float4*)g_denom1)[t] = z;
        ((float4*)g_denom2)[t] = z;
    }
}

// ---------------- GEMM 1: y1 = X @ Wc1   (M=100000, K=128, N=128), FFMA2 ----------------
__global__ __launch_bounds__(256) void sgemm1_kernel(const float* __restrict__ A, int M) {
    constexpr int BM = 128, BK = 8, TM = 8;
    __shared__ float As[BK][BM];
    __shared__ float Bs[BK][128];

    int tid = threadIdx.x;
    int blockRow = blockIdx.x * BM;

    int aRow = tid >> 1;            // 0..127
    int aCol = (tid & 1) * 4;       // 0 or 4
    int bRow = tid >> 5;            // 0..7
    int bCol = (tid & 31) * 4;      // 0..124

    int tRow = (tid >> 4) * TM;
    int tCol = (tid & 15) * 8;

    uint64_t acc[TM][4];
#pragma unroll
    for (int i = 0; i < TM; i++)
#pragma unroll
        for (int j = 0; j < 4; j++) acc[i][j] = 0ull;

    for (int k0 = 0; k0 < 128; k0 += BK) {
        float4 av = make_float4(0.f, 0.f, 0.f, 0.f);
        int gr = blockRow + aRow;
        if (gr < M) av = *(const float4*)(A + (size_t)gr * 128 + k0 + aCol);
        As[aCol + 0][aRow] = av.x;
        As[aCol + 1][aRow] = av.y;
        As[aCol + 2][aRow] = av.z;
        As[aCol + 3][aRow] = av.w;

        *(float4*)(&Bs[bRow][bCol]) = *(const float4*)(g_Wc1 + (size_t)(k0 + bRow) * 128 + bCol);
        __syncthreads();

#pragma unroll
        for (int k = 0; k < BK; k++) {
            uint64_t ap[TM];
#pragma unroll
            for (int i = 0; i < TM; i++) ap[i] = pack_dup(As[k][tRow + i]);
            uint64_t bp[4];
#pragma unroll
            for (int j = 0; j < 4; j++) bp[j] = *(const uint64_t*)(&Bs[k][tCol + 2 * j]);
#pragma unroll
            for (int i = 0; i < TM; i++)
#pragma unroll
                for (int j = 0; j < 4; j++) ffma2(acc[i][j], ap[i], bp[j]);
        }
        __syncthreads();
    }

#pragma unroll
    for (int i = 0; i < TM; i++) {
        int gr = blockRow + tRow + i;
        if (gr < M) {
            float4 o0, o1;
            unpack2(acc[i][0], o0.x, o0.y);
            unpack2(acc[i][1], o0.z, o0.w);
            unpack2(acc[i][2], o1.x, o1.y);
            unpack2(acc[i][3], o1.z, o1.w);
            *(float4*)(g_y1 + (size_t)gr * 128 + tCol)     = o0;
            *(float4*)(g_y1 + (size_t)gr * 128 + tCol + 4) = o1;
        }
    }
}

// ---------------- edge index fetch ----------------
__device__ __forceinline__ void load_edge(const void* ei, int e, int& src, int& dst) {
    if (e >= E_EDGES) { src = dst = e - E_EDGES; return; }
    if (g_idx64) {
        const long long* p = (const long long*)ei;
        src = (int)p[e];
        dst = (int)p[(size_t)E_EDGES + e];
    } else {
        const int* p = (const int*)ei;
        src = p[e];
        dst = p[E_EDGES + e];
    }
}

__device__ __forceinline__ float lrelu(float x) { return x > 0.f ? x : NEG_SLOPE * x; }

// ---------------- edge pass 1: 16 lanes / edge ----------------
__global__ __launch_bounds__(256) void edge1_kernel(const void* __restrict__ ei,
                                                    const float* __restrict__ a1) {
    int g = blockIdx.x * blockDim.x + threadIdx.x;
    int e = g >> 4;
    int lane = g & 15;
    if (e >= TOT_E) return;

    int src, dst;
    load_edge(ei, e, src, dst);

    float4 xl = *(const float4*)(g_y1 + (size_t)src * 128 + lane * 4);
    float4 xr = *(const float4*)(g_y1 + (size_t)dst * 128 + 64 + lane * 4);
    float4 av = *(const float4*)(a1 + lane * 4);

    float p = lrelu(xl.x + xr.x) * av.x;
    p = fmaf(lrelu(xl.y + xr.y), av.y, p);
    p = fmaf(lrelu(xl.z + xr.z), av.z, p);
    p = fmaf(lrelu(xl.w + xr.w), av.w, p);

    p += __shfl_xor_sync(0xffffffffu, p, 8);
    p += __shfl_xor_sync(0xffffffffu, p, 4);
    p += __shfl_xor_sync(0xffffffffu, p, 2);
    p += __shfl_xor_sync(0xffffffffu, p, 1);

    float w = __expf(p);   // max-free softmax: |p| tiny, fp32-safe

    if (lane == 0) atomicAdd(g_denom1 + dst, w);

    float4 contrib = make_float4(w * xl.x, w * xl.y, w * xl.z, w * xl.w);
    atomicAdd((float4*)(g_acc1 + (size_t)dst * 64 + lane * 4), contrib);
}

// ---------------- GEMM 2 (fused ELU epilogue of layer 1): y2 = elu(acc1/denom1+b1) @ Wc2 ----------------
__global__ __launch_bounds__(256) void gemm2_kernel(const float* __restrict__ b1) {
    __shared__ float Ws[64 * 32];
    for (int i = threadIdx.x; i < 64 * 32; i += blockDim.x) Ws[i] = g_Wc2[i];
    __syncthreads();

    int row = (blockIdx.x * blockDim.x + threadIdx.x) >> 5;
    int lane = threadIdx.x & 31;
    if (row >= N_NODES) return;

    float inv = 1.f / g_denom1[row];
    float x0 = fmaf(g_acc1[(size_t)row * 64 + lane],      inv, b1[lane]);
    float x1 = fmaf(g_acc1[(size_t)row * 64 + 32 + lane], inv, b1[lane + 32]);
    float h0 = x0 > 0.f ? x0 : expm1f(x0);
    float h1 = x1 > 0.f ? x1 : expm1f(x1);

    float acc = 0.f;
#pragma unroll
    for (int k = 0; k < 32; k++) {
        float hv = __shfl_sync(0xffffffffu, h0, k);
        acc = fmaf(hv, Ws[k * 32 + lane], acc);
    }
#pragma unroll
    for (int k = 0; k < 32; k++) {
        float hv = __shfl_sync(0xffffffffu, h1, k);
        acc = fmaf(hv, Ws[(k + 32) * 32 + lane], acc);
    }
    g_y2[(size_t)row * 32 + lane] = acc;
}

// ---------------- edge pass 2: 4 lanes / edge ----------------
__global__ __launch_bounds__(256) void edge2_kernel(const void* __restrict__ ei,
                                                    const float* __restrict__ a2) {
    int g = blockIdx.x * blockDim.x + threadIdx.x;
    int e = g >> 2;
    int lane = g & 3;
    if (e >= TOT_E) return;

    int src, dst;
    load_edge(ei, e, src, dst);

    float4 xl = *(const float4*)(g_y2 + (size_t)src * 32 + lane * 4);
    float4 xr = *(const float4*)(g_y2 + (size_t)dst * 32 + 16 + lane * 4);
    float4 av = *(const float4*)(a2 + lane * 4);

    float p = lrelu(xl.x + xr.x) * av.x;
    p = fmaf(lrelu(xl.y + xr.y), av.y, p);
    p = fmaf(lrelu(xl.z + xr.z), av.z, p);
    p = fmaf(lrelu(xl.w + xr.w), av.w, p);

    p += __shfl_xor_sync(0xffffffffu, p, 2);
    p += __shfl_xor_sync(0xffffffffu, p, 1);

    float w = __expf(p);

    if (lane == 0) atomicAdd(g_denom2 + dst, w);

    float4 contrib = make_float4(w * xl.x, w * xl.y, w * xl.z, w * xl.w);
    atomicAdd((float4*)(g_acc2 + (size_t)dst * 16 + lane * 4), contrib);
}

// ---------------- final: softmax(acc2/denom2 + b2) over 16 classes ----------------
__global__ __launch_bounds__(256) void final_kernel(const float* __restrict__ b2,
                                                    float* __restrict__ out) {
    int t = blockIdx.x * blockDim.x + threadIdx.x;
    if (t >= N_NODES * 16) return;
    int i = t >> 4, l = t & 15;

    float v = g_acc2[(size_t)i * 16 + l] / g_denom2[i] + b2[l];

    float m = v;
    m = fmaxf(m, __shfl_xor_sync(0xffffffffu, m, 8));
    m = fmaxf(m, __shfl_xor_sync(0xffffffffu, m, 4));
    m = fmaxf(m, __shfl_xor_sync(0xffffffffu, m, 2));
    m = fmaxf(m, __shfl_xor_sync(0xffffffffu, m, 1));

    float ex = __expf(v - m);
    float s = ex;
    s += __shfl_xor_sync(0xffffffffu, s, 8);
    s += __shfl_xor_sync(0xffffffffu, s, 4);
    s += __shfl_xor_sync(0xffffffffu, s, 2);
    s += __shfl_xor_sync(0xffffffffu, s, 1);

    out[t] = ex / s;
}

// ---------------- launch ----------------
extern "C" void kernel_launch(void* const* d_in, const int* in_sizes, int n_in,
                              void* d_out, int out_size) {
    const float* X   = (const float*)d_in[0];
    const void*  ei  = d_in[1];
    // d_in[2] = batch (unused)
    const float* W1l = (const float*)d_in[3];
    const float* W1r = (const float*)d_in[4];
    const float* a1  = (const float*)d_in[5];
    const float* b1  = (const float*)d_in[6];
    const float* W2l = (const float*)d_in[7];
    const float* W2r = (const float*)d_in[8];
    const float* a2  = (const float*)d_in[9];
    const float* b2  = (const float*)d_in[10];
    float* out = (float*)d_out;

    detect_idx_kernel<<<1, 1>>>(ei);
    pack_w_kernel<<<64, 256>>>(W1l, W1r, W2l, W2r);
    zero_all_kernel<<<(N_NODES * 64 / 4 + 255) / 256, 256>>>();

    sgemm1_kernel<<<(N_NODES + 127) / 128, 256>>>(X, N_NODES);

    {
        long long threads = (long long)TOT_E * 16;
        edge1_kernel<<<(unsigned)((threads + 255) / 256), 256>>>(ei, a1);
    }

    gemm2_kernel<<<(N_NODES * 32 + 255) / 256, 256>>>(b1);

    {
        long long threads = (long long)TOT_E * 4;
        edge2_kernel<<<(unsigned)((threads + 255) / 256), 256>>>(ei, a2);
    }

    final_kernel<<<(N_NODES * 16 + 255) / 256, 256>>>(b2, out);
}